// round 1
// baseline (speedup 1.0000x reference)
#include <cuda_runtime.h>
#include <cuda_bf16.h>
#include <math.h>

// Problem constants
#define SL 2048
#define BSZ 2
#define DM 1024
#define NH 16
#define HD 64
#define MROWS (SL * BSZ)   // 4096

// Scratch (static device globals — allocation-free)
__device__ float g_Q[MROWS * DM];
__device__ float g_K[MROWS * DM];
__device__ float g_V[MROWS * DM];
__device__ float g_A[MROWS * DM];

// ---------------------------------------------------------------------------
// SGEMM-TN:  C[M,N] = A[M,K] @ B[N,K]^T
// A row-major [M,K], B row-major [N,K] (torch Linear weight layout).
// 128x128 block tile, BK=8, 256 threads, 8x8 per-thread micro-tile.
// ---------------------------------------------------------------------------
__global__ __launch_bounds__(256) void sgemm_tn(
    const float* __restrict__ A,
    const float* __restrict__ B,
    float* __restrict__ C,
    int M, int N, int K)
{
    __shared__ float As[8][128];
    __shared__ float Bs[8][128];

    const int tid = threadIdx.x;
    const int tx = tid & 15;        // 0..15  -> N micro
    const int ty = tid >> 4;        // 0..15  -> M micro
    const int bm = blockIdx.y * 128;
    const int bn = blockIdx.x * 128;

    const int lrow = tid >> 1;          // 0..127
    const int lk4  = (tid & 1) * 4;     // 0 or 4

    const float* Ag = A + (size_t)(bm + lrow) * K + lk4;
    const float* Bg = B + (size_t)(bn + lrow) * K + lk4;

    float acc[8][8];
#pragma unroll
    for (int i = 0; i < 8; i++)
#pragma unroll
        for (int j = 0; j < 8; j++) acc[i][j] = 0.0f;

    for (int k0 = 0; k0 < K; k0 += 8) {
        float4 av = *(const float4*)(Ag + k0);
        float4 bv = *(const float4*)(Bg + k0);
        As[lk4 + 0][lrow] = av.x;
        As[lk4 + 1][lrow] = av.y;
        As[lk4 + 2][lrow] = av.z;
        As[lk4 + 3][lrow] = av.w;
        Bs[lk4 + 0][lrow] = bv.x;
        Bs[lk4 + 1][lrow] = bv.y;
        Bs[lk4 + 2][lrow] = bv.z;
        Bs[lk4 + 3][lrow] = bv.w;
        __syncthreads();

#pragma unroll
        for (int k = 0; k < 8; k++) {
            float a[8], b[8];
            *(float4*)(a)     = *(const float4*)&As[k][ty * 8];
            *(float4*)(a + 4) = *(const float4*)&As[k][ty * 8 + 4];
            *(float4*)(b)     = *(const float4*)&Bs[k][tx * 8];
            *(float4*)(b + 4) = *(const float4*)&Bs[k][tx * 8 + 4];
#pragma unroll
            for (int i = 0; i < 8; i++)
#pragma unroll
                for (int j = 0; j < 8; j++)
                    acc[i][j] = fmaf(a[i], b[j], acc[i][j]);
        }
        __syncthreads();
    }

#pragma unroll
    for (int i = 0; i < 8; i++) {
        float* crow = C + (size_t)(bm + ty * 8 + i) * N + bn + tx * 8;
        *(float4*)(crow)     = *(const float4*)&acc[i][0];
        *(float4*)(crow + 4) = *(const float4*)&acc[i][4];
    }
}

// ---------------------------------------------------------------------------
// Flash attention (fp32, no score scaling per reference).
// grid: (SL/128, BSZ*NH), 128 threads. One thread = one query row.
// Q/ACC live in registers; K/V tiles (32 x 64) in shared; every shared read
// in the compute phases is a warp-uniform broadcast -> FMA-bound.
// Layout of Q/K/V buffers: [s][b][h*64+d] (row = s*BSZ+b, 1024 floats).
// ---------------------------------------------------------------------------
__global__ __launch_bounds__(128) void fattn(
    const float* __restrict__ Q,
    const float* __restrict__ K,
    const float* __restrict__ V,
    float* __restrict__ O)
{
    const int bh = blockIdx.y;
    const int b = bh / NH;
    const int h = bh % NH;
    const int tid = threadIdx.x;
    const int qidx = blockIdx.x * 128 + tid;

    __shared__ float Ks[32][64];
    __shared__ float Vs[32][64];

    // load this thread's query row into registers
    float q[64];
    {
        const float4* qp = (const float4*)(Q + ((size_t)qidx * BSZ + b) * DM + h * HD);
#pragma unroll
        for (int i = 0; i < 16; i++) ((float4*)q)[i] = qp[i];
    }

    float acc[64];
#pragma unroll
    for (int d = 0; d < 64; d++) acc[d] = 0.0f;
    float m = -1e30f;
    float l = 0.0f;

    for (int t = 0; t < SL; t += 32) {
        // cooperative load of K/V tile (32 rows x 64 floats each)
#pragma unroll
        for (int i = 0; i < 4; i++) {
            int idx = i * 128 + tid;        // 0..511
            int row = idx >> 4;             // 0..31
            int c4  = (idx & 15) * 4;       // 0..60
            size_t goff = ((size_t)(t + row) * BSZ + b) * DM + h * HD + c4;
            *(float4*)&Ks[row][c4] = *(const float4*)(K + goff);
            *(float4*)&Vs[row][c4] = *(const float4*)(V + goff);
        }
        __syncthreads();

        // scores for 32 keys (all Ks reads are warp broadcasts)
        float s[32];
#pragma unroll
        for (int j = 0; j < 32; j += 4) {
            float s0 = 0.f, s1 = 0.f, s2 = 0.f, s3 = 0.f;
#pragma unroll
            for (int k = 0; k < 64; k++) {
                float qk = q[k];
                s0 = fmaf(qk, Ks[j + 0][k], s0);
                s1 = fmaf(qk, Ks[j + 1][k], s1);
                s2 = fmaf(qk, Ks[j + 2][k], s2);
                s3 = fmaf(qk, Ks[j + 3][k], s3);
            }
            s[j + 0] = s0; s[j + 1] = s1; s[j + 2] = s2; s[j + 3] = s3;
        }

        // online softmax update
        float tmax = s[0];
#pragma unroll
        for (int j = 1; j < 32; j++) tmax = fmaxf(tmax, s[j]);
        float mnew = fmaxf(m, tmax);
        float corr = __expf(m - mnew);
        l *= corr;
#pragma unroll
        for (int d = 0; d < 64; d++) acc[d] *= corr;
#pragma unroll
        for (int j = 0; j < 32; j++) {
            float p = __expf(s[j] - mnew);
            l += p;
#pragma unroll
            for (int d = 0; d < 64; d++)
                acc[d] = fmaf(p, Vs[j][d], acc[d]);
        }
        m = mnew;
        __syncthreads();
    }

    float inv = 1.0f / l;
    float* op = O + ((size_t)qidx * BSZ + b) * DM + h * HD;
#pragma unroll
    for (int i = 0; i < 16; i++) {
        float4 v;
        v.x = acc[i * 4 + 0] * inv;
        v.y = acc[i * 4 + 1] * inv;
        v.z = acc[i * 4 + 2] * inv;
        v.w = acc[i * 4 + 3] * inv;
        ((float4*)op)[i] = v;
    }
}

// ---------------------------------------------------------------------------
extern "C" void kernel_launch(void* const* d_in, const int* in_sizes, int n_in,
                              void* d_out, int out_size)
{
    const float* query = (const float*)d_in[0];
    const float* keys  = (const float*)d_in[1];
    const float* values= (const float*)d_in[2];
    const float* Wq    = (const float*)d_in[3];
    const float* Wk    = (const float*)d_in[4];
    const float* Wv    = (const float*)d_in[5];
    const float* Wo    = (const float*)d_in[6];
    float* out = (float*)d_out;

    float *Qb, *Kb, *Vb, *Ab;
    cudaGetSymbolAddress((void**)&Qb, g_Q);
    cudaGetSymbolAddress((void**)&Kb, g_K);
    cudaGetSymbolAddress((void**)&Vb, g_V);
    cudaGetSymbolAddress((void**)&Ab, g_A);

    dim3 gg(DM / 128, MROWS / 128);   // (8, 32)
    dim3 gb(256);

    sgemm_tn<<<gg, gb>>>(query,  Wq, Qb, MROWS, DM, DM);
    sgemm_tn<<<gg, gb>>>(keys,   Wk, Kb, MROWS, DM, DM);
    sgemm_tn<<<gg, gb>>>(values, Wv, Vb, MROWS, DM, DM);

    dim3 fg(SL / 128, BSZ * NH);      // (16, 32)
    fattn<<<fg, 128>>>(Qb, Kb, Vb, Ab);

    sgemm_tn<<<gg, gb>>>(Ab, Wo, out, MROWS, DM, DM);
}

// round 3
// speedup vs baseline: 1.2881x; 1.2881x over previous
#include <cuda_runtime.h>
#include <cuda_bf16.h>
#include <cstdint>
#include <math.h>

// Problem constants
#define SL 2048
#define BSZ 2
#define DM 1024
#define NH 16
#define HD 64
#define MROWS (SL * BSZ)   // 4096

// Scratch (static device globals — allocation-free)
__device__ float g_Q[MROWS * DM];
__device__ float g_K[MROWS * DM];
__device__ float g_V[MROWS * DM];
__device__ float g_A[MROWS * DM];

// ===========================================================================
// tf32 mma.sync helpers (arch-generic PTX, maps to fallback HMMA on sm_103)
// ===========================================================================
__device__ __forceinline__ uint32_t f2tf32(float x) {
    uint32_t r;
    asm("cvt.rna.tf32.f32 %0, %1;" : "=r"(r) : "f"(x));
    return r;
}

__device__ __forceinline__ void mma_tf32(float c[4], const uint32_t a[4],
                                         const uint32_t b[2]) {
    asm volatile(
        "mma.sync.aligned.m16n8k8.row.col.f32.tf32.tf32.f32 "
        "{%0,%1,%2,%3}, {%4,%5,%6,%7}, {%8,%9}, {%0,%1,%2,%3};"
        : "+f"(c[0]), "+f"(c[1]), "+f"(c[2]), "+f"(c[3])
        : "r"(a[0]), "r"(a[1]), "r"(a[2]), "r"(a[3]), "r"(b[0]), "r"(b[1]));
}

// ===========================================================================
// Tensor-core GEMM-TN:  C[M,N] = A[M,K] @ B[N,K]^T   (M=4096, N=K=1024)
// fp32 in/out, tf32 mma accumulation in fp32.
// CTA 128x128, BK=32, 256 threads = 8 warps in 2(M)x4(N); warp tile 64x32.
// SMEM rows padded to 36 floats -> fragment LDS bank = (4r+c)%32, conflict-free.
// Double-buffered; next chunk prefetched into registers behind the MMAs.
// grid = (N/128, M/128, nz); z selects one of up to 3 independent GEMMs.
// ===========================================================================
#define PADK 36
#define TILE_WORDS (128 * PADK)                 // 4608 words = 18432 B
#define GSMEM_BYTES (4 * TILE_WORDS * 4)        // 73728 B

__global__ void __launch_bounds__(256, 1) gemm_mma(
    const float* __restrict__ A0, const float* __restrict__ B0, float* __restrict__ C0,
    const float* __restrict__ A1, const float* __restrict__ B1, float* __restrict__ C1,
    const float* __restrict__ A2, const float* __restrict__ B2, float* __restrict__ C2)
{
    extern __shared__ float sm[];
    float* Asb[2] = { sm,                  sm + TILE_WORDS };
    float* Bsb[2] = { sm + 2 * TILE_WORDS, sm + 3 * TILE_WORDS };

    const int tid  = threadIdx.x;
    const int wid  = tid >> 5;
    const int lane = tid & 31;
    const int grp  = lane >> 2;    // 0..7
    const int qid  = lane & 3;     // 0..3

    const int z = blockIdx.z;
    const float* A = (z == 0) ? A0 : (z == 1) ? A1 : A2;
    const float* B = (z == 0) ? B0 : (z == 1) ? B1 : B2;
    float*       C = (z == 0) ? C0 : (z == 1) ? C1 : C2;

    const int bm = blockIdx.y * 128;
    const int bn = blockIdx.x * 128;
    const int wm = (wid & 1) * 64;   // warp M offset within CTA tile
    const int wn = (wid >> 1) * 32;  // warp N offset within CTA tile

    // gmem->smem mapping: 1024 float4 slots per tile, 4 per thread
    const int lrow = tid >> 1;            // unused helper removed
    (void)lrow;

    float c[4][4][4];
#pragma unroll
    for (int i = 0; i < 4; i++)
#pragma unroll
        for (int j = 0; j < 4; j++)
#pragma unroll
            for (int v = 0; v < 4; v++) c[i][j][v] = 0.0f;

    // ---- load K-chunk 0 into buffer 0 ----
#pragma unroll
    for (int i = 0; i < 4; i++) {
        int idx = tid + i * 256;          // 0..1023
        int row = idx >> 3;               // 0..127
        int c4  = (idx & 7) * 4;          // 0..28
        *(float4*)&Asb[0][row * PADK + c4] =
            *(const float4*)(A + (size_t)(bm + row) * DM + c4);
        *(float4*)&Bsb[0][row * PADK + c4] =
            *(const float4*)(B + (size_t)(bn + row) * DM + c4);
    }
    __syncthreads();

    float4 pa[4], pb[4];

    for (int kt = 0; kt < DM / 32; kt++) {
        const int cur = kt & 1;
        const bool more = (kt + 1) < DM / 32;

        // prefetch next chunk into registers (latency hidden by MMAs below)
        if (more) {
            const int koff = (kt + 1) * 32;
#pragma unroll
            for (int i = 0; i < 4; i++) {
                int idx = tid + i * 256;
                int row = idx >> 3;
                int c4  = (idx & 7) * 4;
                pa[i] = *(const float4*)(A + (size_t)(bm + row) * DM + koff + c4);
                pb[i] = *(const float4*)(B + (size_t)(bn + row) * DM + koff + c4);
            }
        }

        // compute 4 k8 steps on current buffer
        const float* As = Asb[cur];
        const float* Bs = Bsb[cur];
#pragma unroll
        for (int ks = 0; ks < 4; ks++) {
            const int k0 = ks * 8;
            uint32_t af[4][4], bf[4][2];
#pragma unroll
            for (int mf = 0; mf < 4; mf++) {
                const int r0 = wm + mf * 16 + grp;
                af[mf][0] = f2tf32(As[(r0    ) * PADK + k0 + qid    ]);
                af[mf][1] = f2tf32(As[(r0 + 8) * PADK + k0 + qid    ]);
                af[mf][2] = f2tf32(As[(r0    ) * PADK + k0 + qid + 4]);
                af[mf][3] = f2tf32(As[(r0 + 8) * PADK + k0 + qid + 4]);
            }
#pragma unroll
            for (int nf = 0; nf < 4; nf++) {
                const int n0 = wn + nf * 8 + grp;
                bf[nf][0] = f2tf32(Bs[n0 * PADK + k0 + qid    ]);
                bf[nf][1] = f2tf32(Bs[n0 * PADK + k0 + qid + 4]);
            }
#pragma unroll
            for (int mf = 0; mf < 4; mf++)
#pragma unroll
                for (int nf = 0; nf < 4; nf++)
                    mma_tf32(c[mf][nf], af[mf], bf[nf]);
        }

        // store prefetched chunk into the other buffer
        if (more) {
            float* An = Asb[cur ^ 1];
            float* Bn = Bsb[cur ^ 1];
#pragma unroll
            for (int i = 0; i < 4; i++) {
                int idx = tid + i * 256;
                int row = idx >> 3;
                int c4  = (idx & 7) * 4;
                *(float4*)&An[row * PADK + c4] = pa[i];
                *(float4*)&Bn[row * PADK + c4] = pb[i];
            }
        }
        __syncthreads();
    }

    // ---- epilogue: fragment -> gmem (float2 stores) ----
#pragma unroll
    for (int mf = 0; mf < 4; mf++) {
        const int r0 = bm + wm + mf * 16 + grp;
#pragma unroll
        for (int nf = 0; nf < 4; nf++) {
            const int col = bn + wn + nf * 8 + 2 * qid;
            float2 v0 = make_float2(c[mf][nf][0], c[mf][nf][1]);
            float2 v1 = make_float2(c[mf][nf][2], c[mf][nf][3]);
            *(float2*)(C + (size_t)r0 * DM + col)       = v0;
            *(float2*)(C + (size_t)(r0 + 8) * DM + col) = v1;
        }
    }
}

// ---------------------------------------------------------------------------
// Flash attention (fp32, no score scaling per reference). Unchanged.
// ---------------------------------------------------------------------------
__global__ __launch_bounds__(128) void fattn(
    const float* __restrict__ Q,
    const float* __restrict__ K,
    const float* __restrict__ V,
    float* __restrict__ O)
{
    const int bh = blockIdx.y;
    const int b = bh / NH;
    const int h = bh % NH;
    const int tid = threadIdx.x;
    const int qidx = blockIdx.x * 128 + tid;

    __shared__ float Ks[32][64];
    __shared__ float Vs[32][64];

    float q[64];
    {
        const float4* qp = (const float4*)(Q + ((size_t)qidx * BSZ + b) * DM + h * HD);
#pragma unroll
        for (int i = 0; i < 16; i++) ((float4*)q)[i] = qp[i];
    }

    float acc[64];
#pragma unroll
    for (int d = 0; d < 64; d++) acc[d] = 0.0f;
    float m = -1e30f;
    float l = 0.0f;

    for (int t = 0; t < SL; t += 32) {
#pragma unroll
        for (int i = 0; i < 4; i++) {
            int idx = i * 128 + tid;
            int row = idx >> 4;
            int c4  = (idx & 15) * 4;
            size_t goff = ((size_t)(t + row) * BSZ + b) * DM + h * HD + c4;
            *(float4*)&Ks[row][c4] = *(const float4*)(K + goff);
            *(float4*)&Vs[row][c4] = *(const float4*)(V + goff);
        }
        __syncthreads();

        float s[32];
#pragma unroll
        for (int j = 0; j < 32; j += 4) {
            float s0 = 0.f, s1 = 0.f, s2 = 0.f, s3 = 0.f;
#pragma unroll
            for (int k = 0; k < 64; k++) {
                float qk = q[k];
                s0 = fmaf(qk, Ks[j + 0][k], s0);
                s1 = fmaf(qk, Ks[j + 1][k], s1);
                s2 = fmaf(qk, Ks[j + 2][k], s2);
                s3 = fmaf(qk, Ks[j + 3][k], s3);
            }
            s[j + 0] = s0; s[j + 1] = s1; s[j + 2] = s2; s[j + 3] = s3;
        }

        float tmax = s[0];
#pragma unroll
        for (int j = 1; j < 32; j++) tmax = fmaxf(tmax, s[j]);
        float mnew = fmaxf(m, tmax);
        float corr = __expf(m - mnew);
        l *= corr;
#pragma unroll
        for (int d = 0; d < 64; d++) acc[d] *= corr;
#pragma unroll
        for (int j = 0; j < 32; j++) {
            float p = __expf(s[j] - mnew);
            l += p;
#pragma unroll
            for (int d = 0; d < 64; d++)
                acc[d] = fmaf(p, Vs[j][d], acc[d]);
        }
        m = mnew;
        __syncthreads();
    }

    float inv = 1.0f / l;
    float* op = O + ((size_t)qidx * BSZ + b) * DM + h * HD;
#pragma unroll
    for (int i = 0; i < 16; i++) {
        float4 v;
        v.x = acc[i * 4 + 0] * inv;
        v.y = acc[i * 4 + 1] * inv;
        v.z = acc[i * 4 + 2] * inv;
        v.w = acc[i * 4 + 3] * inv;
        ((float4*)op)[i] = v;
    }
}

// ---------------------------------------------------------------------------
extern "C" void kernel_launch(void* const* d_in, const int* in_sizes, int n_in,
                              void* d_out, int out_size)
{
    const float* query  = (const float*)d_in[0];
    const float* keys   = (const float*)d_in[1];
    const float* values = (const float*)d_in[2];
    const float* Wq     = (const float*)d_in[3];
    const float* Wk     = (const float*)d_in[4];
    const float* Wv     = (const float*)d_in[5];
    const float* Wo     = (const float*)d_in[6];
    float* out = (float*)d_out;

    float *Qb, *Kb, *Vb, *Ab;
    cudaGetSymbolAddress((void**)&Qb, g_Q);
    cudaGetSymbolAddress((void**)&Kb, g_K);
    cudaGetSymbolAddress((void**)&Vb, g_V);
    cudaGetSymbolAddress((void**)&Ab, g_A);

    cudaFuncSetAttribute(gemm_mma, cudaFuncAttributeMaxDynamicSharedMemorySize,
                         GSMEM_BYTES);

    // fused Q/K/V projections
    dim3 gq(DM / 128, MROWS / 128, 3);   // (8, 32, 3)
    gemm_mma<<<gq, 256, GSMEM_BYTES>>>(query,  Wq, Qb,
                                       keys,   Wk, Kb,
                                       values, Wv, Vb);

    dim3 fg(SL / 128, BSZ * NH);         // (16, 32)
    fattn<<<fg, 128>>>(Qb, Kb, Vb, Ab);

    // output projection
    dim3 go(DM / 128, MROWS / 128, 1);   // (8, 32, 1)
    gemm_mma<<<go, 256, GSMEM_BYTES>>>(Ab, Wo, out, Ab, Wo, out, Ab, Wo, out);
}